// round 1
// baseline (speedup 1.0000x reference)
#include <cuda_runtime.h>
#include <math.h>

#define BATCH 16
#define HH 256
#define WW 256
#define HW (HH*WW)
#define HID 64
#define C_NN 4
#define C_CO 4
#define FT_C 2
#define CIN0 6          /* C_NN + FT_C */
#define NTAP0 (CIN0*9)  /* 54 */
#define OUTC (C_CO*4)   /* 16 */

// Scratch for hidden features, NCHW: [b][c][y][x]
__device__ float g_hidden[(size_t)BATCH * HID * HW];

// ---------------------------------------------------------------------------
// Kernel A: fused conv0(3x3,6->64,relu) + 4x (1x1 64->64, relu) -> g_hidden
// Weights in dynamic shared memory (80.6 KB), hidden vector in registers.
// ---------------------------------------------------------------------------
extern __shared__ float smemA[];

__global__ void __launch_bounds__(256, 1) knet(
    const float* __restrict__ input, const float* __restrict__ ft,
    const float* __restrict__ w0, const float* __restrict__ b0,
    const float* __restrict__ w1, const float* __restrict__ b1,
    const float* __restrict__ w2, const float* __restrict__ b2,
    const float* __restrict__ w3, const float* __restrict__ b3,
    const float* __restrict__ w4, const float* __restrict__ b4)
{
    float* sw0 = smemA;                 // transposed: [tap][o], tap=ci*9+ky*3+kx
    float* sw  = smemA + NTAP0 * HID;   // 4 x [j][i] row-major (64x64 each)
    float* sb  = sw + 4 * HID * HID;    // 5 x 64 biases

    const int t = threadIdx.x;
    for (int i = t; i < NTAP0 * HID; i += 256)
        sw0[i] = w0[(i & 63) * NTAP0 + (i >> 6)];
    for (int i = t; i < HID * HID; i += 256) {
        sw[i]          = w1[i];
        sw[4096 + i]   = w2[i];
        sw[8192 + i]   = w3[i];
        sw[12288 + i]  = w4[i];
    }
    if (t < 64) {
        sb[t]       = b0[t];
        sb[64 + t]  = b1[t];
        sb[128 + t] = b2[t];
        sb[192 + t] = b3[t];
        sb[256 + t] = b4[t];
    }
    __syncthreads();

    const int idx = blockIdx.x * 256 + t;
    const int b   = idx >> 16;
    const int y   = (idx >> 8) & 255;
    const int x   = idx & 255;

    float h[HID];
#pragma unroll
    for (int o = 0; o < HID; o++) h[o] = sb[o];

    const float* zb = input + (size_t)b * 8 * HW;
    const float* fb = ft    + (size_t)b * FT_C * HW;

    // conv0: o-inner accumulation so taps never persist
#pragma unroll
    for (int ci = 0; ci < CIN0; ci++) {
        const float* src = (ci < C_NN) ? (zb + ci * HW) : (fb + (ci - C_NN) * HW);
#pragma unroll
        for (int ky = 0; ky < 3; ky++) {
            const int yy = y + ky - 1;
#pragma unroll
            for (int kx = 0; kx < 3; kx++) {
                const int xx = x + kx - 1;
                float vv = 0.f;
                if ((unsigned)yy < HH && (unsigned)xx < WW)
                    vv = __ldg(src + yy * WW + xx);
                const float4* wr = (const float4*)(sw0 + (ci * 9 + ky * 3 + kx) * HID);
#pragma unroll
                for (int q = 0; q < 16; q++) {
                    float4 w4v = wr[q];
                    h[q * 4 + 0] += w4v.x * vv;
                    h[q * 4 + 1] += w4v.y * vv;
                    h[q * 4 + 2] += w4v.z * vv;
                    h[q * 4 + 3] += w4v.w * vv;
                }
            }
        }
    }
#pragma unroll
    for (int o = 0; o < HID; o++) h[o] = fmaxf(h[o], 0.f);

    // 4 x (1x1 64->64 + relu), ping-pong h <-> hn, 2 layers per loop iter
    float hn[HID];
    for (int ll = 0; ll < 2; ll++) {
        {   // layer 2*ll (h -> hn)
            const float* wA = sw + (2 * ll) * 4096;
            const float* bA = sb + (2 * ll + 1) * 64;
#pragma unroll
            for (int j = 0; j < HID; j++) {
                const float4* wr = (const float4*)(wA + j * 64);
                float s0 = bA[j], s1 = 0.f, s2 = 0.f, s3 = 0.f;
#pragma unroll
                for (int q = 0; q < 16; q += 4) {
                    float4 p;
                    p = wr[q + 0]; s0 += p.x*h[4*q+ 0] + p.y*h[4*q+ 1] + p.z*h[4*q+ 2] + p.w*h[4*q+ 3];
                    p = wr[q + 1]; s1 += p.x*h[4*q+ 4] + p.y*h[4*q+ 5] + p.z*h[4*q+ 6] + p.w*h[4*q+ 7];
                    p = wr[q + 2]; s2 += p.x*h[4*q+ 8] + p.y*h[4*q+ 9] + p.z*h[4*q+10] + p.w*h[4*q+11];
                    p = wr[q + 3]; s3 += p.x*h[4*q+12] + p.y*h[4*q+13] + p.z*h[4*q+14] + p.w*h[4*q+15];
                }
                hn[j] = fmaxf((s0 + s1) + (s2 + s3), 0.f);
            }
        }
        {   // layer 2*ll+1 (hn -> h)
            const float* wB = sw + (2 * ll + 1) * 4096;
            const float* bB = sb + (2 * ll + 2) * 64;
#pragma unroll
            for (int j = 0; j < HID; j++) {
                const float4* wr = (const float4*)(wB + j * 64);
                float s0 = bB[j], s1 = 0.f, s2 = 0.f, s3 = 0.f;
#pragma unroll
                for (int q = 0; q < 16; q += 4) {
                    float4 p;
                    p = wr[q + 0]; s0 += p.x*hn[4*q+ 0] + p.y*hn[4*q+ 1] + p.z*hn[4*q+ 2] + p.w*hn[4*q+ 3];
                    p = wr[q + 1]; s1 += p.x*hn[4*q+ 4] + p.y*hn[4*q+ 5] + p.z*hn[4*q+ 6] + p.w*hn[4*q+ 7];
                    p = wr[q + 2]; s2 += p.x*hn[4*q+ 8] + p.y*hn[4*q+ 9] + p.z*hn[4*q+10] + p.w*hn[4*q+11];
                    p = wr[q + 3]; s3 += p.x*hn[4*q+12] + p.y*hn[4*q+13] + p.z*hn[4*q+14] + p.w*hn[4*q+15];
                }
                h[j] = fmaxf((s0 + s1) + (s2 + s3), 0.f);
            }
        }
    }

    const size_t base = ((size_t)b * HID) * HW + (size_t)(y * WW + x);
#pragma unroll
    for (int c = 0; c < HID; c++)
        g_hidden[base + (size_t)c * HW] = h[c];
}

// ---------------------------------------------------------------------------
// Kernel B: convz(3x3, 64->16) on g_hidden + exp(3*logs) scale + RQ spline
// + output assembly + per-batch logdet accumulation.
// ---------------------------------------------------------------------------
__global__ void __launch_bounds__(256) kspline(
    const float* __restrict__ input,
    const float* __restrict__ wz, const float* __restrict__ bz,
    const float* __restrict__ logs,
    float* __restrict__ out)
{
    __shared__ float swz[HID * 9 * OUTC];  // [(c*9+tap)*16 + o]
    __shared__ float sbz[OUTC];
    __shared__ float sscale[OUTC];
    __shared__ float sred[8];

    const int t = threadIdx.y * 32 + threadIdx.x;
    for (int i = t; i < HID * 9 * OUTC; i += 256) {
        const int o  = i & 15;
        const int ct = i >> 4;            // c*9 + tap
        swz[i] = wz[o * (HID * 9) + ct];
    }
    if (t < OUTC) {
        sbz[t]    = bz[t];
        sscale[t] = expf(3.f * logs[t]);
    }
    __syncthreads();

    const int b = blockIdx.z;
    const int y = blockIdx.y * 8 + threadIdx.y;
    const int x = blockIdx.x * 32 + threadIdx.x;

    float acc[OUTC];
#pragma unroll
    for (int o = 0; o < OUTC; o++) acc[o] = 0.f;

    const float* hb = g_hidden + (size_t)b * HID * HW;
#pragma unroll 2
    for (int c = 0; c < HID; c++) {
        const float* hp = hb + (size_t)c * HW;
        float tap[9];
#pragma unroll
        for (int ky = 0; ky < 3; ky++) {
            const int yy = y + ky - 1;
            const bool yv = (unsigned)yy < HH;
#pragma unroll
            for (int kx = 0; kx < 3; kx++) {
                const int xx = x + kx - 1;
                tap[ky * 3 + kx] = (yv && (unsigned)xx < WW) ? __ldg(hp + yy * WW + xx) : 0.f;
            }
        }
        const float* wbase = swz + c * 9 * OUTC;
#pragma unroll
        for (int tt = 0; tt < 9; tt++) {
            const float tv = tap[tt];
            const float4* wr = (const float4*)(wbase + tt * OUTC);
            float4 p0 = wr[0], p1 = wr[1], p2 = wr[2], p3 = wr[3];
            acc[ 0] += p0.x * tv; acc[ 1] += p0.y * tv; acc[ 2] += p0.z * tv; acc[ 3] += p0.w * tv;
            acc[ 4] += p1.x * tv; acc[ 5] += p1.y * tv; acc[ 6] += p1.z * tv; acc[ 7] += p1.w * tv;
            acc[ 8] += p2.x * tv; acc[ 9] += p2.y * tv; acc[10] += p2.z * tv; acc[11] += p2.w * tv;
            acc[12] += p3.x * tv; acc[13] += p3.y * tv; acc[14] += p3.z * tv; acc[15] += p3.w * tv;
        }
    }

    const float* xin  = input + (size_t)b * 8 * HW + (size_t)(y * WW + x);
    float*       oo   = out   + (size_t)b * 8 * HW + (size_t)(y * WW + x);
    float ladsum = 0.f;

#pragma unroll
    for (int co = 0; co < C_CO; co++) {
        const float rw = (acc[co * 4 + 0] + sbz[co * 4 + 0]) * sscale[co * 4 + 0];
        const float rh = (acc[co * 4 + 1] + sbz[co * 4 + 1]) * sscale[co * 4 + 1];
        const float rd = (acc[co * 4 + 2] + sbz[co * 4 + 2]) * sscale[co * 4 + 2];
        const float sh = (acc[co * 4 + 3] + sbz[co * 4 + 3]) * sscale[co * 4 + 3];

        // copy z1 channel
        oo[(size_t)co * HW] = __ldg(xin + (size_t)co * HW);

        const float x2 = __ldg(xin + (size_t)(4 + co) * HW);
        const bool inside = (x2 > -0.5f) && (x2 < 0.5f);
        const float xs = inside ? x2 : 0.f;

        const float width = 1.f / (1.f + expf(-rw)) * 0.998f + 0.001f;
        const float hh    = 1.f / (1.f + expf(-rh)) * 0.998f + 0.001f;
        const float dd    = expf(rd) * 0.999f + 0.001f;

        const float cw1 = width - 0.5f;
        const float ch1 = hh    - 0.5f;
        const bool bin1 = xs >= cw1;

        const float in_cw = bin1 ? cw1 : -0.5f;
        const float in_w  = bin1 ? (0.5f - cw1) : (cw1 + 0.5f);
        const float in_ch = bin1 ? ch1 : -0.5f;
        const float in_h  = bin1 ? (0.5f - ch1) : (ch1 + 0.5f);
        const float d0    = bin1 ? dd : 1.f;
        const float d1    = bin1 ? 1.f : dd;

        const float delta = in_h / in_w;
        const float theta = (xs - in_cw) / in_w;
        const float omt   = 1.f - theta;
        const float t1mt  = theta * omt;
        const float denom = delta + (d0 + d1 - 2.f * delta) * t1mt;
        float outv = in_ch + in_h * (delta * theta * theta + d0 * t1mt) / denom;
        const float dnum = delta * delta * (d1 * theta * theta + 2.f * delta * t1mt + d0 * omt * omt);
        const float lad  = logf(dnum) - 2.f * logf(denom);
        outv = fminf(fmaxf(outv, -0.5f), 0.5f);

        oo[(size_t)(4 + co) * HW] = (inside ? outv : x2) + sh;
        ladsum += inside ? lad : 0.f;
    }

    // block-reduce ladsum, one atomic per block (block is within one batch b)
#pragma unroll
    for (int off = 16; off; off >>= 1)
        ladsum += __shfl_down_sync(0xffffffffu, ladsum, off);
    const int warp = t >> 5;
    if ((t & 31) == 0) sred[warp] = ladsum;
    __syncthreads();
    if (t < 8) {
        float v = sred[t];
#pragma unroll
        for (int off = 4; off; off >>= 1)
            v += __shfl_down_sync(0xffu, v, off);
        if (t == 0) atomicAdd(out + (size_t)BATCH * 8 * HW + b, v);
    }
}

// Seed the logdet outputs from the input logdet (d_out is poisoned).
__global__ void kinit(const float* __restrict__ logdet, float* __restrict__ out)
{
    const int t = threadIdx.x;
    if (t < BATCH) out[(size_t)BATCH * 8 * HW + t] = logdet[t];
}

// ---------------------------------------------------------------------------
extern "C" void kernel_launch(void* const* d_in, const int* in_sizes, int n_in,
                              void* d_out, int out_size)
{
    const float* input  = (const float*)d_in[0];
    const float* logdet = (const float*)d_in[1];
    const float* ft     = (const float*)d_in[2];
    const float* w0     = (const float*)d_in[3];
    const float* b0     = (const float*)d_in[4];
    const float* w1     = (const float*)d_in[5];
    const float* b1     = (const float*)d_in[6];
    const float* w2     = (const float*)d_in[7];
    const float* b2     = (const float*)d_in[8];
    const float* w3     = (const float*)d_in[9];
    const float* b3     = (const float*)d_in[10];
    const float* w4     = (const float*)d_in[11];
    const float* b4     = (const float*)d_in[12];
    const float* wz     = (const float*)d_in[13];
    const float* bz     = (const float*)d_in[14];
    const float* logs   = (const float*)d_in[15];
    float* out = (float*)d_out;

    const size_t smemA_bytes = (size_t)(NTAP0 * HID + 4 * HID * HID + 5 * HID) * sizeof(float);
    cudaFuncSetAttribute(knet, cudaFuncAttributeMaxDynamicSharedMemorySize, (int)smemA_bytes);

    kinit<<<1, 32>>>(logdet, out);

    knet<<<(BATCH * HW) / 256, 256, smemA_bytes>>>(
        input, ft, w0, b0, w1, b1, w2, b2, w3, b3, w4, b4);

    dim3 blk(32, 8, 1);
    dim3 grd(WW / 32, HH / 8, BATCH);
    kspline<<<grd, blk>>>(input, wz, bz, logs, out);
}

// round 2
// speedup vs baseline: 1.1229x; 1.1229x over previous
#include <cuda_runtime.h>
#include <math.h>

#define BATCH 16
#define HH 256
#define WW 256
#define HW (HH*WW)
#define HID 64
#define C_NN 4
#define C_CO 4
#define FT_C 2
#define CIN0 6          /* C_NN + FT_C */
#define NTAP0 (CIN0*9)  /* 54 */
#define OUTC (C_CO*4)   /* 16 */

typedef unsigned long long ull;

// ---------------------------------------------------------------------------
// Packed f32x2 helpers (FFMA2 path — ptxas only emits these from explicit PTX)
// ---------------------------------------------------------------------------
__device__ __forceinline__ ull ffma2(ull a, ull b, ull c) {
    ull d;
    asm("fma.rn.f32x2 %0, %1, %2, %3;" : "=l"(d) : "l"(a), "l"(b), "l"(c));
    return d;
}
__device__ __forceinline__ ull add2(ull a, ull b) {
    ull d;
    asm("add.rn.f32x2 %0, %1, %2;" : "=l"(d) : "l"(a), "l"(b));
    return d;
}
__device__ __forceinline__ ull pack2(float lo, float hi) {
    ull d;
    asm("mov.b64 %0, {%1, %2};" : "=l"(d)
        : "r"(__float_as_uint(lo)), "r"(__float_as_uint(hi)));
    return d;
}
__device__ __forceinline__ void unpack2(ull v, float& lo, float& hi) {
    unsigned int a, b;
    asm("mov.b64 {%0, %1}, %2;" : "=r"(a), "=r"(b) : "l"(v));
    lo = __uint_as_float(a); hi = __uint_as_float(b);
}

// Scratch for hidden features, NCHW: [b][c][y][x]
__device__ float g_hidden[(size_t)BATCH * HID * HW];

// ---------------------------------------------------------------------------
// Kernel A: fused conv0(3x3,6->64,relu) + 4x (1x1 64->64, relu) -> g_hidden
// Hidden vector lives as 32 packed f32x2 registers; all MACs via FFMA2.
// ---------------------------------------------------------------------------
extern __shared__ float smemA[];

__global__ void __launch_bounds__(256) knet(
    const float* __restrict__ input, const float* __restrict__ ft,
    const float* __restrict__ w0, const float* __restrict__ b0,
    const float* __restrict__ w1, const float* __restrict__ b1,
    const float* __restrict__ w2, const float* __restrict__ b2,
    const float* __restrict__ w3, const float* __restrict__ b3,
    const float* __restrict__ w4, const float* __restrict__ b4)
{
    float* sw0 = smemA;                 // transposed: [tap][o], tap=ci*9+ky*3+kx
    float* sw  = smemA + NTAP0 * HID;   // 4 x [j][i] row-major (64x64 each)
    float* sb  = sw + 4 * HID * HID;    // 5 x 64 biases

    const int t = threadIdx.x;
    for (int i = t; i < NTAP0 * HID; i += 256)
        sw0[i] = w0[(i & 63) * NTAP0 + (i >> 6)];
    for (int i = t; i < HID * HID; i += 256) {
        sw[i]          = w1[i];
        sw[4096 + i]   = w2[i];
        sw[8192 + i]   = w3[i];
        sw[12288 + i]  = w4[i];
    }
    if (t < 64) {
        sb[t]       = b0[t];
        sb[64 + t]  = b1[t];
        sb[128 + t] = b2[t];
        sb[192 + t] = b3[t];
        sb[256 + t] = b4[t];
    }
    __syncthreads();

    const int idx = blockIdx.x * 256 + t;
    const int b   = idx >> 16;
    const int y   = (idx >> 8) & 255;
    const int x   = idx & 255;

    ull hA[32], hB[32];   // packed pairs: hA[k] = (ch 2k, ch 2k+1)

#pragma unroll
    for (int k = 0; k < 32; k++) hA[k] = pack2(sb[2 * k], sb[2 * k + 1]);

    const float* zb = input + (size_t)b * 8 * HW;
    const float* fb = ft    + (size_t)b * FT_C * HW;

    // conv0: accumulators packed along output channel; tap duplicated once.
#pragma unroll
    for (int ci = 0; ci < CIN0; ci++) {
        const float* src = (ci < C_NN) ? (zb + ci * HW) : (fb + (ci - C_NN) * HW);
#pragma unroll
        for (int ky = 0; ky < 3; ky++) {
            const int yy = y + ky - 1;
#pragma unroll
            for (int kx = 0; kx < 3; kx++) {
                const int xx = x + kx - 1;
                float vv = 0.f;
                if ((unsigned)yy < HH && (unsigned)xx < WW)
                    vv = __ldg(src + yy * WW + xx);
                const ull vv2 = pack2(vv, vv);
                const ulonglong2* wr =
                    (const ulonglong2*)(sw0 + (ci * 9 + ky * 3 + kx) * HID);
#pragma unroll
                for (int q = 0; q < 16; q++) {
                    ulonglong2 w2v = wr[q];
                    hA[2 * q]     = ffma2(w2v.x, vv2, hA[2 * q]);
                    hA[2 * q + 1] = ffma2(w2v.y, vv2, hA[2 * q + 1]);
                }
            }
        }
    }
    // relu (packed -> unpack/max/repack)
#pragma unroll
    for (int k = 0; k < 32; k++) {
        float lo, hi; unpack2(hA[k], lo, hi);
        hA[k] = pack2(fmaxf(lo, 0.f), fmaxf(hi, 0.f));
    }

    // 1x1 layers: SRC packed along input dim, two outputs per iteration.
#define LAYER(SRC, DST, WBASE, BBASE)                                          \
    _Pragma("unroll 4")                                                        \
    for (int jp = 0; jp < 32; jp++) {                                          \
        const ulonglong2* w0r = (const ulonglong2*)((WBASE) + (2*jp)   * HID); \
        const ulonglong2* w1r = (const ulonglong2*)((WBASE) + (2*jp+1) * HID); \
        ull s0a = 0ull, s0b = 0ull, s1a = 0ull, s1b = 0ull;                    \
        _Pragma("unroll")                                                      \
        for (int q = 0; q < 16; q++) {                                         \
            ulonglong2 wv0 = w0r[q];                                           \
            ulonglong2 wv1 = w1r[q];                                           \
            s0a = ffma2(wv0.x, SRC[2*q],     s0a);                             \
            s0b = ffma2(wv0.y, SRC[2*q + 1], s0b);                             \
            s1a = ffma2(wv1.x, SRC[2*q],     s1a);                             \
            s1b = ffma2(wv1.y, SRC[2*q + 1], s1b);                             \
        }                                                                      \
        float l0, h0c, l1, h1c;                                                \
        unpack2(add2(s0a, s0b), l0, h0c);                                      \
        unpack2(add2(s1a, s1b), l1, h1c);                                      \
        DST[jp] = pack2(fmaxf(l0 + h0c + (BBASE)[2*jp],     0.f),              \
                        fmaxf(l1 + h1c + (BBASE)[2*jp + 1], 0.f));             \
    }

    LAYER(hA, hB, sw,          sb + 64)
    LAYER(hB, hA, sw + 4096,   sb + 128)
    LAYER(hA, hB, sw + 8192,   sb + 192)
    LAYER(hB, hA, sw + 12288,  sb + 256)
#undef LAYER

    const size_t base = ((size_t)b * HID) * HW + (size_t)(y * WW + x);
#pragma unroll
    for (int k = 0; k < 32; k++) {
        float lo, hi; unpack2(hA[k], lo, hi);
        g_hidden[base + (size_t)(2 * k)     * HW] = lo;
        g_hidden[base + (size_t)(2 * k + 1) * HW] = hi;
    }
}

// ---------------------------------------------------------------------------
// Kernel B: convz(3x3, 64->16) on g_hidden + exp(3*logs) scale + RQ spline
// Accumulators packed along the 16 output channels (8 f32x2 pairs).
// ---------------------------------------------------------------------------
__global__ void __launch_bounds__(256) kspline(
    const float* __restrict__ input,
    const float* __restrict__ wz, const float* __restrict__ bz,
    const float* __restrict__ logs,
    float* __restrict__ out)
{
    __shared__ float swz[HID * 9 * OUTC];  // [(c*9+tap)*16 + o]
    __shared__ float sbz[OUTC];
    __shared__ float sscale[OUTC];
    __shared__ float sred[8];

    const int t = threadIdx.y * 32 + threadIdx.x;
    for (int i = t; i < HID * 9 * OUTC; i += 256) {
        const int o  = i & 15;
        const int ct = i >> 4;            // c*9 + tap
        swz[i] = wz[o * (HID * 9) + ct];
    }
    if (t < OUTC) {
        sbz[t]    = bz[t];
        sscale[t] = expf(3.f * logs[t]);
    }
    __syncthreads();

    const int b = blockIdx.z;
    const int y = blockIdx.y * 8 + threadIdx.y;
    const int x = blockIdx.x * 32 + threadIdx.x;

    ull accp[8];   // accp[k] = outputs (2k, 2k+1)
#pragma unroll
    for (int k = 0; k < 8; k++) accp[k] = 0ull;

    const float* hb = g_hidden + (size_t)b * HID * HW;
#pragma unroll 2
    for (int c = 0; c < HID; c++) {
        const float* hp = hb + (size_t)c * HW;
        float tap[9];
#pragma unroll
        for (int ky = 0; ky < 3; ky++) {
            const int yy = y + ky - 1;
            const bool yv = (unsigned)yy < HH;
#pragma unroll
            for (int kx = 0; kx < 3; kx++) {
                const int xx = x + kx - 1;
                tap[ky * 3 + kx] = (yv && (unsigned)xx < WW) ? __ldg(hp + yy * WW + xx) : 0.f;
            }
        }
        const float* wbase = swz + c * 9 * OUTC;
#pragma unroll
        for (int tt = 0; tt < 9; tt++) {
            const ull tv2 = pack2(tap[tt], tap[tt]);
            const ulonglong2* wr = (const ulonglong2*)(wbase + tt * OUTC);
            ulonglong2 p0 = wr[0], p1 = wr[1];
            accp[0] = ffma2(p0.x, tv2, accp[0]);
            accp[1] = ffma2(p0.y, tv2, accp[1]);
            accp[2] = ffma2(p1.x, tv2, accp[2]);
            accp[3] = ffma2(p1.y, tv2, accp[3]);
            ulonglong2 p2 = wr[2], p3 = wr[3];
            accp[4] = ffma2(p2.x, tv2, accp[4]);
            accp[5] = ffma2(p2.y, tv2, accp[5]);
            accp[6] = ffma2(p3.x, tv2, accp[6]);
            accp[7] = ffma2(p3.y, tv2, accp[7]);
        }
    }

    float acc[OUTC];
#pragma unroll
    for (int k = 0; k < 8; k++) unpack2(accp[k], acc[2 * k], acc[2 * k + 1]);

    const float* xin  = input + (size_t)b * 8 * HW + (size_t)(y * WW + x);
    float*       oo   = out   + (size_t)b * 8 * HW + (size_t)(y * WW + x);
    float ladsum = 0.f;

#pragma unroll
    for (int co = 0; co < C_CO; co++) {
        const float rw = (acc[co * 4 + 0] + sbz[co * 4 + 0]) * sscale[co * 4 + 0];
        const float rh = (acc[co * 4 + 1] + sbz[co * 4 + 1]) * sscale[co * 4 + 1];
        const float rd = (acc[co * 4 + 2] + sbz[co * 4 + 2]) * sscale[co * 4 + 2];
        const float sh = (acc[co * 4 + 3] + sbz[co * 4 + 3]) * sscale[co * 4 + 3];

        // copy z1 channel
        oo[(size_t)co * HW] = __ldg(xin + (size_t)co * HW);

        const float x2 = __ldg(xin + (size_t)(4 + co) * HW);
        const bool inside = (x2 > -0.5f) && (x2 < 0.5f);
        const float xs = inside ? x2 : 0.f;

        const float width = 1.f / (1.f + expf(-rw)) * 0.998f + 0.001f;
        const float hh    = 1.f / (1.f + expf(-rh)) * 0.998f + 0.001f;
        const float dd    = expf(rd) * 0.999f + 0.001f;

        const float cw1 = width - 0.5f;
        const float ch1 = hh    - 0.5f;
        const bool bin1 = xs >= cw1;

        const float in_cw = bin1 ? cw1 : -0.5f;
        const float in_w  = bin1 ? (0.5f - cw1) : (cw1 + 0.5f);
        const float in_ch = bin1 ? ch1 : -0.5f;
        const float in_h  = bin1 ? (0.5f - ch1) : (ch1 + 0.5f);
        const float d0    = bin1 ? dd : 1.f;
        const float d1    = bin1 ? 1.f : dd;

        const float delta = in_h / in_w;
        const float theta = (xs - in_cw) / in_w;
        const float omt   = 1.f - theta;
        const float t1mt  = theta * omt;
        const float denom = delta + (d0 + d1 - 2.f * delta) * t1mt;
        float outv = in_ch + in_h * (delta * theta * theta + d0 * t1mt) / denom;
        const float dnum = delta * delta * (d1 * theta * theta + 2.f * delta * t1mt + d0 * omt * omt);
        const float lad  = logf(dnum) - 2.f * logf(denom);
        outv = fminf(fmaxf(outv, -0.5f), 0.5f);

        oo[(size_t)(4 + co) * HW] = (inside ? outv : x2) + sh;
        ladsum += inside ? lad : 0.f;
    }

    // block-reduce ladsum, one atomic per block (block is within one batch b)
#pragma unroll
    for (int off = 16; off; off >>= 1)
        ladsum += __shfl_down_sync(0xffffffffu, ladsum, off);
    const int warp = t >> 5;
    if ((t & 31) == 0) sred[warp] = ladsum;
    __syncthreads();
    if (t < 8) {
        float v = sred[t];
#pragma unroll
        for (int off = 4; off; off >>= 1)
            v += __shfl_down_sync(0xffu, v, off);
        if (t == 0) atomicAdd(out + (size_t)BATCH * 8 * HW + b, v);
    }
}

// Seed the logdet outputs from the input logdet (d_out is poisoned).
__global__ void kinit(const float* __restrict__ logdet, float* __restrict__ out)
{
    const int t = threadIdx.x;
    if (t < BATCH) out[(size_t)BATCH * 8 * HW + t] = logdet[t];
}

// ---------------------------------------------------------------------------
extern "C" void kernel_launch(void* const* d_in, const int* in_sizes, int n_in,
                              void* d_out, int out_size)
{
    const float* input  = (const float*)d_in[0];
    const float* logdet = (const float*)d_in[1];
    const float* ft     = (const float*)d_in[2];
    const float* w0     = (const float*)d_in[3];
    const float* b0     = (const float*)d_in[4];
    const float* w1     = (const float*)d_in[5];
    const float* b1     = (const float*)d_in[6];
    const float* w2     = (const float*)d_in[7];
    const float* b2     = (const float*)d_in[8];
    const float* w3     = (const float*)d_in[9];
    const float* b3     = (const float*)d_in[10];
    const float* w4     = (const float*)d_in[11];
    const float* b4     = (const float*)d_in[12];
    const float* wz     = (const float*)d_in[13];
    const float* bz     = (const float*)d_in[14];
    const float* logs   = (const float*)d_in[15];
    float* out = (float*)d_out;

    const size_t smemA_bytes = (size_t)(NTAP0 * HID + 4 * HID * HID + 5 * HID) * sizeof(float);
    cudaFuncSetAttribute(knet, cudaFuncAttributeMaxDynamicSharedMemorySize, (int)smemA_bytes);

    kinit<<<1, 32>>>(logdet, out);

    knet<<<(BATCH * HW) / 256, 256, smemA_bytes>>>(
        input, ft, w0, b0, w1, b1, w2, b2, w3, b3, w4, b4);

    dim3 blk(32, 8, 1);
    dim3 grd(WW / 32, HH / 8, BATCH);
    kspline<<<grd, blk>>>(input, wz, bz, logs, out);
}

// round 3
// speedup vs baseline: 1.3450x; 1.1978x over previous
#include <cuda_runtime.h>
#include <math.h>

#define BATCH 16
#define HH 256
#define WW 256
#define HW (HH*WW)
#define HID 64
#define C_NN 4
#define C_CO 4
#define FT_C 2
#define CIN0 6          /* C_NN + FT_C */
#define NTAP0 (CIN0*9)  /* 54 */
#define OUTC (C_CO*4)   /* 16 */

typedef unsigned long long ull;

// ---------------------------------------------------------------------------
// Packed f32x2 helpers (FFMA2 path)
// ---------------------------------------------------------------------------
__device__ __forceinline__ ull ffma2(ull a, ull b, ull c) {
    ull d;
    asm("fma.rn.f32x2 %0, %1, %2, %3;" : "=l"(d) : "l"(a), "l"(b), "l"(c));
    return d;
}
__device__ __forceinline__ ull add2(ull a, ull b) {
    ull d;
    asm("add.rn.f32x2 %0, %1, %2;" : "=l"(d) : "l"(a), "l"(b));
    return d;
}
__device__ __forceinline__ ull pack2(float lo, float hi) {
    ull d;
    asm("mov.b64 %0, {%1, %2};" : "=l"(d)
        : "r"(__float_as_uint(lo)), "r"(__float_as_uint(hi)));
    return d;
}
__device__ __forceinline__ void unpack2(ull v, float& lo, float& hi) {
    unsigned int a, b;
    asm("mov.b64 {%0, %1}, %2;" : "=r"(a), "=r"(b) : "l"(v));
    lo = __uint_as_float(a); hi = __uint_as_float(b);
}

// Scratch
__device__ float g_hidden[(size_t)BATCH * HID * HW];
__device__ __align__(16) float g_w0t[NTAP0 * HID];   // transposed conv0 weights [tap][o]

// ---------------------------------------------------------------------------
// Prep: transpose conv0 weights [o][tap] -> [tap][o]
// ---------------------------------------------------------------------------
__global__ void ktrans(const float* __restrict__ w0)
{
    const int i = blockIdx.x * 256 + threadIdx.x;
    if (i < NTAP0 * HID) {
        const int tap = i >> 6;
        const int o   = i & 63;
        g_w0t[tap * HID + o] = w0[o * NTAP0 + tap];
    }
}

// ---------------------------------------------------------------------------
// Kernel A: fused conv0(3x3,6->64,relu) + 4x (1x1 64->64, relu) -> g_hidden
// 2 threads per pixel (each owns 32 channels); halves exchanged via shared.
// 256 threads = 128 pixels. Forced 2 blocks/SM for 16 warps of occupancy.
// ---------------------------------------------------------------------------
extern __shared__ float smemA[];

__global__ void __launch_bounds__(256, 2) knet(
    const float* __restrict__ input, const float* __restrict__ ft,
    const float* __restrict__ b0,
    const float* __restrict__ w1, const float* __restrict__ b1,
    const float* __restrict__ w2, const float* __restrict__ b2,
    const float* __restrict__ w3, const float* __restrict__ b3,
    const float* __restrict__ w4, const float* __restrict__ b4)
{
    float* sw = smemA;                  // 4 x [j][i] row-major (64x64 each)
    float* sb = smemA + 4 * HID * HID;  // 5 x 64 biases
    ull*   sx = (ull*)(sb + 5 * HID);   // exchange: [32 ch-pairs][128 pixels]

    const int t = threadIdx.x;
    for (int i = t; i < HID * HID; i += 256) {
        sw[i]          = w1[i];
        sw[4096 + i]   = w2[i];
        sw[8192 + i]   = w3[i];
        sw[12288 + i]  = w4[i];
    }
    if (t < 64) {
        sb[t]       = b0[t];
        sb[64 + t]  = b1[t];
        sb[128 + t] = b2[t];
        sb[192 + t] = b3[t];
        sb[256 + t] = b4[t];
    }
    __syncthreads();

    const int p    = t & 127;
    const int half = t >> 7;
    const int idx  = blockIdx.x * 128 + p;
    const int b    = idx >> 16;
    const int y    = (idx >> 8) & 255;
    const int x    = idx & 255;
    const int cb   = half * 32;          // my channel base

    ull out[16];                         // my 32 channels as 16 packed pairs
#pragma unroll
    for (int k = 0; k < 16; k++) out[k] = pack2(sb[cb + 2 * k], sb[cb + 2 * k + 1]);

    const float* zb = input + (size_t)b * 8 * HW;
    const float* fb = ft    + (size_t)b * FT_C * HW;

    // conv0: tap broadcast, weights from transposed global table (L1 broadcast)
#pragma unroll
    for (int ci = 0; ci < CIN0; ci++) {
        const float* src = (ci < C_NN) ? (zb + ci * HW) : (fb + (ci - C_NN) * HW);
#pragma unroll
        for (int ky = 0; ky < 3; ky++) {
            const int yy = y + ky - 1;
#pragma unroll
            for (int kx = 0; kx < 3; kx++) {
                const int xx = x + kx - 1;
                float vv = 0.f;
                if ((unsigned)yy < HH && (unsigned)xx < WW)
                    vv = __ldg(src + yy * WW + xx);
                const ull vv2 = pack2(vv, vv);
                const ulonglong2* wr =
                    (const ulonglong2*)(g_w0t + (ci * 9 + ky * 3 + kx) * HID + cb);
#pragma unroll
                for (int q = 0; q < 8; q++) {
                    ulonglong2 wv = wr[q];
                    out[2 * q]     = ffma2(wv.x, vv2, out[2 * q]);
                    out[2 * q + 1] = ffma2(wv.y, vv2, out[2 * q + 1]);
                }
            }
        }
    }
#pragma unroll
    for (int k = 0; k < 16; k++) {
        float lo, hi; unpack2(out[k], lo, hi);
        out[k] = pack2(fmaxf(lo, 0.f), fmaxf(hi, 0.f));
    }

    // 4 x (1x1 64->64 + relu): exchange halves through shared each layer
#pragma unroll 1
    for (int l = 0; l < 4; l++) {
        const float* wl = sw + l * 4096;
        const float* bl = sb + 64 + l * 64;

#pragma unroll
        for (int k = 0; k < 16; k++)
            sx[(half * 16 + k) * 128 + p] = out[k];
        __syncthreads();

        ull src[32];                      // full 64-ch input vector
#pragma unroll
        for (int k = 0; k < 32; k++)
            src[k] = sx[k * 128 + p];
        __syncthreads();                  // buffer free for next layer's writes

#pragma unroll 2
        for (int jp = 0; jp < 16; jp++) {
            const int j0 = cb + 2 * jp;
            const ulonglong2* w0r = (const ulonglong2*)(wl + j0 * 64);
            const ulonglong2* w1r = (const ulonglong2*)(wl + j0 * 64 + 64);
            ull s0a = 0ull, s0b = 0ull, s1a = 0ull, s1b = 0ull;
#pragma unroll
            for (int q = 0; q < 16; q++) {
                ulonglong2 wv0 = w0r[q];
                ulonglong2 wv1 = w1r[q];
                s0a = ffma2(wv0.x, src[2 * q],     s0a);
                s0b = ffma2(wv0.y, src[2 * q + 1], s0b);
                s1a = ffma2(wv1.x, src[2 * q],     s1a);
                s1b = ffma2(wv1.y, src[2 * q + 1], s1b);
            }
            float l0, h0c, l1, h1c;
            unpack2(add2(s0a, s0b), l0, h0c);
            unpack2(add2(s1a, s1b), l1, h1c);
            out[jp] = pack2(fmaxf(l0 + h0c + bl[j0],     0.f),
                            fmaxf(l1 + h1c + bl[j0 + 1], 0.f));
        }
    }

    const size_t base = ((size_t)b * HID) * HW + (size_t)(y * WW + x);
#pragma unroll
    for (int k = 0; k < 16; k++) {
        float lo, hi; unpack2(out[k], lo, hi);
        g_hidden[base + (size_t)(cb + 2 * k)     * HW] = lo;
        g_hidden[base + (size_t)(cb + 2 * k + 1) * HW] = hi;
    }
}

// ---------------------------------------------------------------------------
// Kernel B: convz(3x3, 64->16) on g_hidden + exp(3*logs) scale + RQ spline
// ---------------------------------------------------------------------------
__global__ void __launch_bounds__(256) kspline(
    const float* __restrict__ input,
    const float* __restrict__ wz, const float* __restrict__ bz,
    const float* __restrict__ logs,
    float* __restrict__ out)
{
    __shared__ float swz[HID * 9 * OUTC];  // [(c*9+tap)*16 + o]
    __shared__ float sbz[OUTC];
    __shared__ float sscale[OUTC];
    __shared__ float sred[8];

    const int t = threadIdx.y * 32 + threadIdx.x;
    for (int i = t; i < HID * 9 * OUTC; i += 256) {
        const int o  = i & 15;
        const int ct = i >> 4;            // c*9 + tap
        swz[i] = wz[o * (HID * 9) + ct];
    }
    if (t < OUTC) {
        sbz[t]    = bz[t];
        sscale[t] = expf(3.f * logs[t]);
    }
    __syncthreads();

    const int b = blockIdx.z;
    const int y = blockIdx.y * 8 + threadIdx.y;
    const int x = blockIdx.x * 32 + threadIdx.x;

    ull accp[8];   // accp[k] = outputs (2k, 2k+1)
#pragma unroll
    for (int k = 0; k < 8; k++) accp[k] = 0ull;

    const float* hb = g_hidden + (size_t)b * HID * HW;
#pragma unroll 2
    for (int c = 0; c < HID; c++) {
        const float* hp = hb + (size_t)c * HW;
        float tap[9];
#pragma unroll
        for (int ky = 0; ky < 3; ky++) {
            const int yy = y + ky - 1;
            const bool yv = (unsigned)yy < HH;
#pragma unroll
            for (int kx = 0; kx < 3; kx++) {
                const int xx = x + kx - 1;
                tap[ky * 3 + kx] = (yv && (unsigned)xx < WW) ? __ldg(hp + yy * WW + xx) : 0.f;
            }
        }
        const float* wbase = swz + c * 9 * OUTC;
#pragma unroll
        for (int tt = 0; tt < 9; tt++) {
            const ull tv2 = pack2(tap[tt], tap[tt]);
            const ulonglong2* wr = (const ulonglong2*)(wbase + tt * OUTC);
            ulonglong2 p0 = wr[0], p1 = wr[1];
            accp[0] = ffma2(p0.x, tv2, accp[0]);
            accp[1] = ffma2(p0.y, tv2, accp[1]);
            accp[2] = ffma2(p1.x, tv2, accp[2]);
            accp[3] = ffma2(p1.y, tv2, accp[3]);
            ulonglong2 p2 = wr[2], p3 = wr[3];
            accp[4] = ffma2(p2.x, tv2, accp[4]);
            accp[5] = ffma2(p2.y, tv2, accp[5]);
            accp[6] = ffma2(p3.x, tv2, accp[6]);
            accp[7] = ffma2(p3.y, tv2, accp[7]);
        }
    }

    float acc[OUTC];
#pragma unroll
    for (int k = 0; k < 8; k++) unpack2(accp[k], acc[2 * k], acc[2 * k + 1]);

    const float* xin  = input + (size_t)b * 8 * HW + (size_t)(y * WW + x);
    float*       oo   = out   + (size_t)b * 8 * HW + (size_t)(y * WW + x);
    float ladsum = 0.f;

#pragma unroll
    for (int co = 0; co < C_CO; co++) {
        const float rw = (acc[co * 4 + 0] + sbz[co * 4 + 0]) * sscale[co * 4 + 0];
        const float rh = (acc[co * 4 + 1] + sbz[co * 4 + 1]) * sscale[co * 4 + 1];
        const float rd = (acc[co * 4 + 2] + sbz[co * 4 + 2]) * sscale[co * 4 + 2];
        const float sh = (acc[co * 4 + 3] + sbz[co * 4 + 3]) * sscale[co * 4 + 3];

        // copy z1 channel
        oo[(size_t)co * HW] = __ldg(xin + (size_t)co * HW);

        const float x2 = __ldg(xin + (size_t)(4 + co) * HW);
        const bool inside = (x2 > -0.5f) && (x2 < 0.5f);
        const float xs = inside ? x2 : 0.f;

        const float width = 1.f / (1.f + expf(-rw)) * 0.998f + 0.001f;
        const float hh    = 1.f / (1.f + expf(-rh)) * 0.998f + 0.001f;
        const float dd    = expf(rd) * 0.999f + 0.001f;

        const float cw1 = width - 0.5f;
        const float ch1 = hh    - 0.5f;
        const bool bin1 = xs >= cw1;

        const float in_cw = bin1 ? cw1 : -0.5f;
        const float in_w  = bin1 ? (0.5f - cw1) : (cw1 + 0.5f);
        const float in_ch = bin1 ? ch1 : -0.5f;
        const float in_h  = bin1 ? (0.5f - ch1) : (ch1 + 0.5f);
        const float d0    = bin1 ? dd : 1.f;
        const float d1    = bin1 ? 1.f : dd;

        const float delta = in_h / in_w;
        const float theta = (xs - in_cw) / in_w;
        const float omt   = 1.f - theta;
        const float t1mt  = theta * omt;
        const float denom = delta + (d0 + d1 - 2.f * delta) * t1mt;
        float outv = in_ch + in_h * (delta * theta * theta + d0 * t1mt) / denom;
        const float dnum = delta * delta * (d1 * theta * theta + 2.f * delta * t1mt + d0 * omt * omt);
        const float lad  = logf(dnum) - 2.f * logf(denom);
        outv = fminf(fmaxf(outv, -0.5f), 0.5f);

        oo[(size_t)(4 + co) * HW] = (inside ? outv : x2) + sh;
        ladsum += inside ? lad : 0.f;
    }

    // block-reduce ladsum, one atomic per block (block is within one batch b)
#pragma unroll
    for (int off = 16; off; off >>= 1)
        ladsum += __shfl_down_sync(0xffffffffu, ladsum, off);
    const int warp = t >> 5;
    if ((t & 31) == 0) sred[warp] = ladsum;
    __syncthreads();
    if (t < 8) {
        float v = sred[t];
#pragma unroll
        for (int off = 4; off; off >>= 1)
            v += __shfl_down_sync(0xffu, v, off);
        if (t == 0) atomicAdd(out + (size_t)BATCH * 8 * HW + b, v);
    }
}

// Seed the logdet outputs from the input logdet (d_out is poisoned).
__global__ void kinit(const float* __restrict__ logdet, float* __restrict__ out)
{
    const int t = threadIdx.x;
    if (t < BATCH) out[(size_t)BATCH * 8 * HW + t] = logdet[t];
}

// ---------------------------------------------------------------------------
extern "C" void kernel_launch(void* const* d_in, const int* in_sizes, int n_in,
                              void* d_out, int out_size)
{
    const float* input  = (const float*)d_in[0];
    const float* logdet = (const float*)d_in[1];
    const float* ft     = (const float*)d_in[2];
    const float* w0     = (const float*)d_in[3];
    const float* b0     = (const float*)d_in[4];
    const float* w1     = (const float*)d_in[5];
    const float* b1     = (const float*)d_in[6];
    const float* w2     = (const float*)d_in[7];
    const float* b2     = (const float*)d_in[8];
    const float* w3     = (const float*)d_in[9];
    const float* b3     = (const float*)d_in[10];
    const float* w4     = (const float*)d_in[11];
    const float* b4     = (const float*)d_in[12];
    const float* wz     = (const float*)d_in[13];
    const float* bz     = (const float*)d_in[14];
    const float* logs   = (const float*)d_in[15];
    float* out = (float*)d_out;

    // smem: 4x 64x64 weights + 5x64 biases + 32x128 ull exchange
    const size_t smemA_bytes = (size_t)(4 * HID * HID + 5 * HID) * sizeof(float)
                             + (size_t)32 * 128 * sizeof(ull);
    cudaFuncSetAttribute(knet, cudaFuncAttributeMaxDynamicSharedMemorySize, (int)smemA_bytes);

    kinit<<<1, 32>>>(logdet, out);
    ktrans<<<(NTAP0 * HID + 255) / 256, 256>>>(w0);

    knet<<<(BATCH * HW) / 128, 256, smemA_bytes>>>(
        input, ft, b0, w1, b1, w2, b2, w3, b3, w4, b4);

    dim3 blk(32, 8, 1);
    dim3 grd(WW / 32, HH / 8, BATCH);
    kspline<<<grd, blk>>>(input, wz, bz, logs, out);
}

// round 5
// speedup vs baseline: 2.2827x; 1.6971x over previous
#include <cuda_runtime.h>
#include <math.h>

#define BATCH 16
#define HH 256
#define WW 256
#define HW (HH*WW)
#define HID 64
#define C_NN 4
#define C_CO 4
#define FT_C 2
#define CIN0 6          /* C_NN + FT_C */
#define NTAP0 (CIN0*9)  /* 54 */
#define OUTC (C_CO*4)   /* 16 */

typedef unsigned long long ull;

// ---------------------------------------------------------------------------
// Packed f32x2 helpers (FFMA2 path)
// ---------------------------------------------------------------------------
__device__ __forceinline__ ull ffma2(ull a, ull b, ull c) {
    ull d;
    asm("fma.rn.f32x2 %0, %1, %2, %3;" : "=l"(d) : "l"(a), "l"(b), "l"(c));
    return d;
}
__device__ __forceinline__ ull pack2(float lo, float hi) {
    ull d;
    asm("mov.b64 %0, {%1, %2};" : "=l"(d)
        : "r"(__float_as_uint(lo)), "r"(__float_as_uint(hi)));
    return d;
}
__device__ __forceinline__ void unpack2(ull v, float& lo, float& hi) {
    unsigned int a, b;
    asm("mov.b64 {%0, %1}, %2;" : "=r"(a), "=r"(b) : "l"(v));
    lo = __uint_as_float(a); hi = __uint_as_float(b);
}

// Scratch
__device__ float g_hidden[(size_t)BATCH * HID * HW];
__device__ __align__(16) float g_w0t[NTAP0 * HID];      // conv0 weights [tap][o]
__device__ __align__(16) float g_wt[4 * HID * HID];     // 1x1 weights  [l][i][j]

// ---------------------------------------------------------------------------
// Prep: transpose conv0 weights [o][tap]->[tap][o] and 1x1 weights [j][i]->[i][j]
// ---------------------------------------------------------------------------
__global__ void kprep(const float* __restrict__ w0,
                      const float* __restrict__ w1, const float* __restrict__ w2,
                      const float* __restrict__ w3, const float* __restrict__ w4)
{
    const int i = blockIdx.x * 256 + threadIdx.x;
    if (i < NTAP0 * HID) {
        const int tap = i >> 6;
        const int o   = i & 63;
        g_w0t[tap * HID + o] = w0[o * NTAP0 + tap];
    }
    if (i < 4 * HID * HID) {
        const int l   = i >> 12;
        const int rem = i & 4095;
        const int ii  = rem >> 6;   // input channel
        const int j   = rem & 63;   // output channel
        const float* w = (l == 0) ? w1 : (l == 1) ? w2 : (l == 2) ? w3 : w4;
        g_wt[i] = w[j * HID + ii];
    }
}

// ---------------------------------------------------------------------------
// Kernel A: conv0 + 4x 1x1, GEMM-retiled.
// Block = 256 threads = 8 ch-groups x 32 px-groups; covers 128 consecutive x.
// Thread: 8 output channels (4 pairs) x 4 pixels (stride-32 -> conflict-free).
// Activations ping-pong in shared; weights via broadcast LDG from global.
// ---------------------------------------------------------------------------
extern __shared__ float smemX[];    // [2][64][128]

__global__ void __launch_bounds__(256, 3) knet(
    const float* __restrict__ input, const float* __restrict__ ft,
    const float* __restrict__ b0, const float* __restrict__ b1,
    const float* __restrict__ b2, const float* __restrict__ b3,
    const float* __restrict__ b4)
{
    float* X0 = smemX;
    float* X1 = smemX + HID * 128;

    const int t  = threadIdx.x;
    const int jg = t >> 5;      // 0..7  : output-channel group (8 ch)
    const int pg = t & 31;      // 0..31 : pixel group (px = pg + 32m)
    const int xs = blockIdx.x;  // 0/1   : x half
    const int y  = blockIdx.y;
    const int b  = blockIdx.z;
    const int xbase = xs * 128;

    // ---- conv0: acc[jp][m], jp = channel pair within my 8, m = px index ----
    ull acc[4][4];
    {
        const ulonglong2* bp = (const ulonglong2*)(b0 + jg * 8);
        ulonglong2 bv0 = bp[0], bv1 = bp[1];
#pragma unroll
        for (int m = 0; m < 4; m++) {
            acc[0][m] = bv0.x; acc[1][m] = bv0.y;
            acc[2][m] = bv1.x; acc[3][m] = bv1.y;
        }
    }

    const float* zb = input + (size_t)b * 8 * HW;
    const float* fb = ft    + (size_t)b * FT_C * HW;

#pragma unroll
    for (int ci = 0; ci < CIN0; ci++) {
        const float* src = (ci < C_NN) ? (zb + ci * HW) : (fb + (ci - C_NN) * HW);
#pragma unroll
        for (int ky = 0; ky < 3; ky++) {
            const int yy = y + ky - 1;
            const bool yv = (unsigned)yy < HH;
            const float* rowp = src + yy * WW;
            float v[4][3];
#pragma unroll
            for (int m = 0; m < 4; m++) {
                const int x = xbase + pg + 32 * m;
                v[m][0] = (yv && x > 0)        ? __ldg(rowp + x - 1) : 0.f;
                v[m][1] = yv                   ? __ldg(rowp + x)     : 0.f;
                v[m][2] = (yv && x < WW - 1)   ? __ldg(rowp + x + 1) : 0.f;
            }
#pragma unroll
            for (int kx = 0; kx < 3; kx++) {
                const ulonglong2* wr =
                    (const ulonglong2*)(g_w0t + (ci * 9 + ky * 3 + kx) * HID + jg * 8);
                ulonglong2 wv0 = wr[0], wv1 = wr[1];
#pragma unroll
                for (int m = 0; m < 4; m++) {
                    const ull td = pack2(v[m][kx], v[m][kx]);
                    acc[0][m] = ffma2(wv0.x, td, acc[0][m]);
                    acc[1][m] = ffma2(wv0.y, td, acc[1][m]);
                    acc[2][m] = ffma2(wv1.x, td, acc[2][m]);
                    acc[3][m] = ffma2(wv1.y, td, acc[3][m]);
                }
            }
        }
    }
    // relu + store to X0
#pragma unroll
    for (int jp = 0; jp < 4; jp++) {
        const int ch = jg * 8 + 2 * jp;
#pragma unroll
        for (int m = 0; m < 4; m++) {
            float a, bb; unpack2(acc[jp][m], a, bb);
            X0[ch * 128 + pg + 32 * m]       = fmaxf(a,  0.f);
            X0[(ch + 1) * 128 + pg + 32 * m] = fmaxf(bb, 0.f);
        }
    }
    __syncthreads();

    // ---- 4 x (1x1 64->64 + relu) ----
#pragma unroll 1
    for (int l = 0; l < 4; l++) {
        const float* Xr = (l & 1) ? X1 : X0;
        float*       Xw = (l & 1) ? X0 : X1;
        const float* wl = g_wt + l * HID * HID + jg * 8;
        const float* bl = (l == 0) ? b1 : (l == 1) ? b2 : (l == 2) ? b3 : b4;

        ull a2[4][4];
#pragma unroll
        for (int jp = 0; jp < 4; jp++)
#pragma unroll
            for (int m = 0; m < 4; m++) a2[jp][m] = 0ull;

#pragma unroll 4
        for (int i = 0; i < HID; i++) {
            const ulonglong2* wr = (const ulonglong2*)(wl + i * HID);
            ulonglong2 wv0 = wr[0], wv1 = wr[1];
            float xv0 = Xr[i * 128 + pg];
            float xv1 = Xr[i * 128 + pg + 32];
            float xv2 = Xr[i * 128 + pg + 64];
            float xv3 = Xr[i * 128 + pg + 96];
            ull d0 = pack2(xv0, xv0), d1 = pack2(xv1, xv1);
            ull d2 = pack2(xv2, xv2), d3 = pack2(xv3, xv3);
            a2[0][0] = ffma2(wv0.x, d0, a2[0][0]);
            a2[1][0] = ffma2(wv0.y, d0, a2[1][0]);
            a2[2][0] = ffma2(wv1.x, d0, a2[2][0]);
            a2[3][0] = ffma2(wv1.y, d0, a2[3][0]);
            a2[0][1] = ffma2(wv0.x, d1, a2[0][1]);
            a2[1][1] = ffma2(wv0.y, d1, a2[1][1]);
            a2[2][1] = ffma2(wv1.x, d1, a2[2][1]);
            a2[3][1] = ffma2(wv1.y, d1, a2[3][1]);
            a2[0][2] = ffma2(wv0.x, d2, a2[0][2]);
            a2[1][2] = ffma2(wv0.y, d2, a2[1][2]);
            a2[2][2] = ffma2(wv1.x, d2, a2[2][2]);
            a2[3][2] = ffma2(wv1.y, d2, a2[3][2]);
            a2[0][3] = ffma2(wv0.x, d3, a2[0][3]);
            a2[1][3] = ffma2(wv0.y, d3, a2[1][3]);
            a2[2][3] = ffma2(wv1.x, d3, a2[2][3]);
            a2[3][3] = ffma2(wv1.y, d3, a2[3][3]);
        }

        const ulonglong2* bp = (const ulonglong2*)(bl + jg * 8);
        ulonglong2 bv0 = bp[0], bv1 = bp[1];
        float bf[8];
        unpack2(bv0.x, bf[0], bf[1]); unpack2(bv0.y, bf[2], bf[3]);
        unpack2(bv1.x, bf[4], bf[5]); unpack2(bv1.y, bf[6], bf[7]);
#pragma unroll
        for (int jp = 0; jp < 4; jp++) {
            const int ch = jg * 8 + 2 * jp;
#pragma unroll
            for (int m = 0; m < 4; m++) {
                float a, bb; unpack2(a2[jp][m], a, bb);
                Xw[ch * 128 + pg + 32 * m]       = fmaxf(a  + bf[2 * jp],     0.f);
                Xw[(ch + 1) * 128 + pg + 32 * m] = fmaxf(bb + bf[2 * jp + 1], 0.f);
            }
        }
        __syncthreads();
    }

    // ---- copy result (in X0 after layer 3) to g_hidden ----
    const size_t gb = ((size_t)b * HID) * HW + (size_t)y * WW + xbase;
#pragma unroll
    for (int it = 0; it < 32; it++) {
        const int idx = it * 256 + t;
        const int ch  = idx >> 7;
        const int pxl = idx & 127;
        g_hidden[gb + (size_t)ch * HW + pxl] = X0[ch * 128 + pxl];
    }
}

// ---------------------------------------------------------------------------
// Kernel B: convz(3x3, 64->16) + spline. Single pass, 4 pixels per thread,
// all 16 output channels (8 f32x2 pairs) accumulated together.
// Warp = one (row, x-half): lane handles 4 consecutive x; halos via shfl.
// ---------------------------------------------------------------------------
__global__ void __launch_bounds__(256, 2) kspline(
    const float* __restrict__ input,
    const float* __restrict__ wz, const float* __restrict__ bz,
    const float* __restrict__ logs,
    float* __restrict__ out)
{
    __shared__ __align__(16) float swz[HID * 9 * OUTC];  // [(c*9+tap)*16 + o]
    __shared__ float sbz[OUTC];
    __shared__ float sscale[OUTC];
    __shared__ float sred[8];

    const int t = threadIdx.x;
    for (int i = t; i < HID * 9 * OUTC; i += 256) {
        const int o  = i & 15;
        const int ct = i >> 4;            // c*9 + tap
        swz[i] = wz[o * (HID * 9) + ct];
    }
    if (t < OUTC) {
        sbz[t]    = bz[t];
        sscale[t] = expf(3.f * logs[t]);
    }
    __syncthreads();

    const int warp = t >> 5;
    const int lane = t & 31;
    const int b  = blockIdx.z;
    const int y  = blockIdx.y * 4 + (warp >> 1);
    const int xh = warp & 1;
    const int x0 = xh * 128 + lane * 4;

    ull accp[4][8];   // [px j][pair p] ; pair p covers out channels (2p, 2p+1)
#pragma unroll
    for (int j = 0; j < 4; j++)
#pragma unroll
        for (int p = 0; p < 8; p++) accp[j][p] = 0ull;

    const float* hb = g_hidden + (size_t)b * HID * HW;

#pragma unroll 1
    for (int c = 0; c < HID; c++) {
        const float* hp = hb + (size_t)c * HW;
        float e[3][6];
#pragma unroll
        for (int r = 0; r < 3; r++) {
            const int yy = y + r - 1;
            const bool yv = (unsigned)yy < HH;
            float4 v;
            if (yv) v = *(const float4*)(hp + yy * WW + x0);
            else    v = make_float4(0.f, 0.f, 0.f, 0.f);
            float lft = __shfl_up_sync(0xffffffffu, v.w, 1);
            float rgt = __shfl_down_sync(0xffffffffu, v.x, 1);
            if (lane == 0)  lft = (yv && x0 > 0)      ? __ldg(hp + yy * WW + x0 - 1) : 0.f;
            if (lane == 31) rgt = (yv && x0 + 4 < WW) ? __ldg(hp + yy * WW + x0 + 4) : 0.f;
            e[r][0] = lft; e[r][1] = v.x; e[r][2] = v.y;
            e[r][3] = v.z; e[r][4] = v.w; e[r][5] = rgt;
        }
#pragma unroll
        for (int r = 0; r < 3; r++) {
#pragma unroll
            for (int kx = 0; kx < 3; kx++) {
                const int tt = r * 3 + kx;
                // 16 weights for this (c, tap): 4 x ulonglong2
                const ulonglong2* wt =
                    (const ulonglong2*)(swz + (c * 9 + tt) * OUTC);
                ulonglong2 wv0 = wt[0], wv1 = wt[1];
                ulonglong2 wv2 = wt[2], wv3 = wt[3];
#pragma unroll
                for (int j = 0; j < 4; j++) {
                    const float ev = e[r][j + kx];
                    const ull d = pack2(ev, ev);
                    accp[j][0] = ffma2(wv0.x, d, accp[j][0]);
                    accp[j][1] = ffma2(wv0.y, d, accp[j][1]);
                    accp[j][2] = ffma2(wv1.x, d, accp[j][2]);
                    accp[j][3] = ffma2(wv1.y, d, accp[j][3]);
                    accp[j][4] = ffma2(wv2.x, d, accp[j][4]);
                    accp[j][5] = ffma2(wv2.y, d, accp[j][5]);
                    accp[j][6] = ffma2(wv3.x, d, accp[j][6]);
                    accp[j][7] = ffma2(wv3.y, d, accp[j][7]);
                }
            }
        }
    }

    // ---- spline epilogue, 4 px per thread ----
    const float* xin = input + (size_t)b * 8 * HW + (size_t)y * WW + x0;
    float*       oo  = out   + (size_t)b * 8 * HW + (size_t)y * WW + x0;
    float ladsum = 0.f;

#pragma unroll
    for (int co = 0; co < C_CO; co++) {
        // copy z1 channel (vectorized)
        *(float4*)(oo + (size_t)co * HW) = *(const float4*)(xin + (size_t)co * HW);

        float4 x2v = *(const float4*)(xin + (size_t)(4 + co) * HW);
        const float x2a[4] = { x2v.x, x2v.y, x2v.z, x2v.w };
        float rs[4];
#pragma unroll
        for (int j = 0; j < 4; j++) {
            float rw, rh, rd, sh;
            unpack2(accp[j][2 * co],     rw, rh);
            unpack2(accp[j][2 * co + 1], rd, sh);
            rw = (rw + sbz[co * 4 + 0]) * sscale[co * 4 + 0];
            rh = (rh + sbz[co * 4 + 1]) * sscale[co * 4 + 1];
            rd = (rd + sbz[co * 4 + 2]) * sscale[co * 4 + 2];
            sh = (sh + sbz[co * 4 + 3]) * sscale[co * 4 + 3];

            const float x2 = x2a[j];
            const bool inside = (x2 > -0.5f) && (x2 < 0.5f);
            const float xs2 = inside ? x2 : 0.f;

            const float width = 1.f / (1.f + expf(-rw)) * 0.998f + 0.001f;
            const float hh2   = 1.f / (1.f + expf(-rh)) * 0.998f + 0.001f;
            const float dd    = expf(rd) * 0.999f + 0.001f;

            const float cw1 = width - 0.5f;
            const float ch1 = hh2   - 0.5f;
            const bool bin1 = xs2 >= cw1;

            const float in_cw = bin1 ? cw1 : -0.5f;
            const float in_w  = bin1 ? (0.5f - cw1) : (cw1 + 0.5f);
            const float in_ch = bin1 ? ch1 : -0.5f;
            const float in_h  = bin1 ? (0.5f - ch1) : (ch1 + 0.5f);
            const float d0    = bin1 ? dd : 1.f;
            const float d1    = bin1 ? 1.f : dd;

            const float delta = in_h / in_w;
            const float theta = (xs2 - in_cw) / in_w;
            const float omt   = 1.f - theta;
            const float t1mt  = theta * omt;
            const float denom = delta + (d0 + d1 - 2.f * delta) * t1mt;
            float outv = in_ch + in_h * (delta * theta * theta + d0 * t1mt) / denom;
            const float dnum = delta * delta *
                (d1 * theta * theta + 2.f * delta * t1mt + d0 * omt * omt);
            const float lad  = logf(dnum) - 2.f * logf(denom);
            outv = fminf(fmaxf(outv, -0.5f), 0.5f);

            rs[j] = (inside ? outv : x2) + sh;
            ladsum += inside ? lad : 0.f;
        }
        *(float4*)(oo + (size_t)(4 + co) * HW) = make_float4(rs[0], rs[1], rs[2], rs[3]);
    }

    // block-reduce ladsum -> one atomic per block
#pragma unroll
    for (int off = 16; off; off >>= 1)
        ladsum += __shfl_down_sync(0xffffffffu, ladsum, off);
    if (lane == 0) sred[warp] = ladsum;
    __syncthreads();
    if (t < 8) {
        float v = sred[t];
#pragma unroll
        for (int off = 4; off; off >>= 1)
            v += __shfl_down_sync(0xffu, v, off);
        if (t == 0) atomicAdd(out + (size_t)BATCH * 8 * HW + b, v);
    }
}

// Seed the logdet outputs from the input logdet (d_out is poisoned).
__global__ void kinit(const float* __restrict__ logdet, float* __restrict__ out)
{
    const int t = threadIdx.x;
    if (t < BATCH) out[(size_t)BATCH * 8 * HW + t] = logdet[t];
}

// ---------------------------------------------------------------------------
extern "C" void kernel_launch(void* const* d_in, const int* in_sizes, int n_in,
                              void* d_out, int out_size)
{
    const float* input  = (const float*)d_in[0];
    const float* logdet = (const float*)d_in[1];
    const float* ft     = (const float*)d_in[2];
    const float* w0     = (const float*)d_in[3];
    const float* b0     = (const float*)d_in[4];
    const float* w1     = (const float*)d_in[5];
    const float* b1     = (const float*)d_in[6];
    const float* w2     = (const float*)d_in[7];
    const float* b2     = (const float*)d_in[8];
    const float* w3     = (const float*)d_in[9];
    const float* b3     = (const float*)d_in[10];
    const float* w4     = (const float*)d_in[11];
    const float* b4     = (const float*)d_in[12];
    const float* wz     = (const float*)d_in[13];
    const float* bz     = (const float*)d_in[14];
    const float* logs   = (const float*)d_in[15];
    float* out = (float*)d_out;

    const size_t smemA_bytes = (size_t)2 * HID * 128 * sizeof(float);   // 64 KB
    cudaFuncSetAttribute(knet, cudaFuncAttributeMaxDynamicSharedMemorySize, (int)smemA_bytes);

    kinit<<<1, 32>>>(logdet, out);
    kprep<<<(4 * HID * HID + 255) / 256, 256>>>(w0, w1, w2, w3, w4);

    dim3 gA(2, 256, 16);
    knet<<<gA, 256, smemA_bytes>>>(input, ft, b0, b1, b2, b3, b4);

    dim3 gB(1, 64, 16);
    kspline<<<gB, 256>>>(input, wz, bz, logs, out);
}